// round 1
// baseline (speedup 1.0000x reference)
#include <cuda_runtime.h>
#include <math.h>

#define N_BATCH 4096
#define D_FEAT  64
#define KDIM    128          // feature dim of packed A/B vectors
#define TILE    64           // block tile (rows of I and of J)
#define KC      32           // k-chunk staged in smem
#define PAD     34           // smem row stride in floats (32 + 2): conflict-free, 8B-aligned
#define NBLK    (N_BATCH / TILE)   // 64

// ---- scratch (static device globals; no allocation allowed) ----
__device__ __align__(256) float g_A[N_BATCH * KDIM];   // [u_i, -2*mu_i]
__device__ __align__(256) float g_B[N_BATCH * KDIM];   // [a_j,  b_j]
__device__ __align__(256) float g_C[N_BATCH];          // c_j  = sum mu^2 * a
__device__ __align__(256) float g_P[N_BATCH];          // p_j  = prod var
__device__ __align__(256) float g_RP[N_BATCH];         // 1/(p+eps)
__device__ double g_acc[2];                            // pos_sum, neg_sum

// ---------------------------------------------------------------
__global__ void init_kernel() {
    g_acc[0] = 0.0;
    g_acc[1] = 0.0;
}

// One block per row, 64 threads (one per feature).
__global__ void precompute_kernel(const float* __restrict__ mu,
                                  const float* __restrict__ var) {
    int row = blockIdx.x;
    int d   = threadIdx.x;
    float v  = var[row * D_FEAT + d];
    float m  = mu [row * D_FEAT + d];
    float iv = 1.0f / v;                       // IEEE divide, matches jnp
    g_A[row * KDIM + d]          = v + m * m;  // u
    g_A[row * KDIM + D_FEAT + d] = -2.0f * m;
    g_B[row * KDIM + d]          = iv;         // a
    g_B[row * KDIM + D_FEAT + d] = m * iv;     // b

    __shared__ float sc[64];
    __shared__ float sp[64];
    sc[d] = m * m * iv;
    sp[d] = v;
    __syncthreads();
    #pragma unroll
    for (int s = 32; s > 0; s >>= 1) {
        if (d < s) { sc[d] += sc[d + s]; sp[d] *= sp[d + s]; }
        __syncthreads();
    }
    if (d == 0) {
        g_C[row]  = sc[0];
        g_P[row]  = sp[0];
        g_RP[row] = 1.0f / (sp[0] + 1e-8f);
    }
}

// ---------------------------------------------------------------
__device__ __forceinline__ void load_tile(float* __restrict__ s,
                                          const float* __restrict__ g,
                                          int baseRow, int k0, int tid) {
    // tile: 64 rows x 32 cols; 512 float4 loads spread over 256 threads
    #pragma unroll
    for (int e = 0; e < 2; e++) {
        int idx = tid + e * 256;
        int r   = idx >> 3;
        int c   = (idx & 7) * 4;
        const float4 v = *(const float4*)(g + (baseRow + r) * KDIM + k0 + c);
        float2* p = (float2*)(s + r * PAD + c);   // r*136B + c*4B -> 8B aligned
        p[0] = make_float2(v.x, v.y);
        p[1] = make_float2(v.z, v.w);
    }
}

__global__ __launch_bounds__(256)
void pair_kernel(const int* __restrict__ labels) {
    int bj = blockIdx.x;   // column block
    int bi = blockIdx.y;   // row block
    if (bi > bj) return;   // upper triangle of blocks only

    __shared__ float AsI[TILE * PAD];
    __shared__ float BsI[TILE * PAD];
    __shared__ float AsJ[TILE * PAD];
    __shared__ float BsJ[TILE * PAD];
    __shared__ float redp[256];
    __shared__ float redn[256];

    int tid = threadIdx.x;
    int tx  = tid & 15;    // j-fragment selector
    int ty  = tid >> 4;    // i-fragment selector

    int baseI = bi * TILE;
    int baseJ = bj * TILE;

    // f32x2 accumulators for S = A_i.B_j + A_j.B_i (two k-lanes each)
    unsigned long long acc[4][4];
    #pragma unroll
    for (int m = 0; m < 4; m++)
        #pragma unroll
        for (int n = 0; n < 4; n++)
            acc[m][n] = 0ull;

    for (int k0 = 0; k0 < KDIM; k0 += KC) {
        __syncthreads();   // previous chunk fully consumed
        load_tile(AsI, g_A, baseI, k0, tid);
        load_tile(BsI, g_B, baseI, k0, tid);
        load_tile(AsJ, g_A, baseJ, k0, tid);
        load_tile(BsJ, g_B, baseJ, k0, tid);
        __syncthreads();

        #pragma unroll
        for (int kk = 0; kk < KC; kk += 2) {
            unsigned long long aI[4], bI[4], aJ[4], bJ[4];
            #pragma unroll
            for (int m = 0; m < 4; m++) {
                int r = ty + 16 * m;
                aI[m] = *(const unsigned long long*)(AsI + r * PAD + kk);
                bI[m] = *(const unsigned long long*)(BsI + r * PAD + kk);
            }
            #pragma unroll
            for (int n = 0; n < 4; n++) {
                int r = tx + 16 * n;
                aJ[n] = *(const unsigned long long*)(AsJ + r * PAD + kk);
                bJ[n] = *(const unsigned long long*)(BsJ + r * PAD + kk);
            }
            #pragma unroll
            for (int m = 0; m < 4; m++)
                #pragma unroll
                for (int n = 0; n < 4; n++) {
                    asm("fma.rn.f32x2 %0, %1, %2, %0;"
                        : "+l"(acc[m][n]) : "l"(aI[m]), "l"(bJ[n]));
                    asm("fma.rn.f32x2 %0, %1, %2, %0;"
                        : "+l"(acc[m][n]) : "l"(aJ[n]), "l"(bI[m]));
                }
        }
    }

    // -------- epilogue: sym -> sigmoid -> masked sums --------
    float ci[4], pi_[4], rpi[4];  int li[4], gi[4];
    float cj[4], pj_[4], rpj[4];  int lj[4], gj[4];
    #pragma unroll
    for (int m = 0; m < 4; m++) {
        int r = baseI + ty + 16 * m;
        gi[m] = r; ci[m] = g_C[r]; pi_[m] = g_P[r]; rpi[m] = g_RP[r]; li[m] = labels[r];
    }
    #pragma unroll
    for (int n = 0; n < 4; n++) {
        int r = baseJ + tx + 16 * n;
        gj[n] = r; cj[n] = g_C[r]; pj_[n] = g_P[r]; rpj[n] = g_RP[r]; lj[n] = labels[r];
    }

    float pos = 0.0f, neg = 0.0f;
    bool offdiag_blk = (bi < bj);
    #pragma unroll
    for (int m = 0; m < 4; m++) {
        #pragma unroll
        for (int n = 0; n < 4; n++) {
            unsigned long long a = acc[m][n];
            float lo = __uint_as_float((unsigned)(a & 0xffffffffull));
            float hi = __uint_as_float((unsigned)(a >> 32));
            float S  = lo + hi;
            float sym = 0.25f * (S + ci[m] + cj[n]
                                 + pj_[n] * rpi[m] + pi_[m] * rpj[n]
                                 - 2.0f * (float)D_FEAT);
            float sig = 1.0f / (1.0f + __expf(-sym));
            float w = offdiag_blk ? 2.0f : ((gi[m] < gj[n]) ? 2.0f : 0.0f);
            if (li[m] == lj[n]) pos += w * sig; else neg += w * sig;
        }
    }

    // block reduction
    redp[tid] = pos; redn[tid] = neg;
    __syncthreads();
    #pragma unroll
    for (int s = 128; s > 0; s >>= 1) {
        if (tid < s) { redp[tid] += redp[tid + s]; redn[tid] += redn[tid + s]; }
        __syncthreads();
    }
    if (tid == 0) {
        atomicAdd(&g_acc[0], (double)redp[0]);
        atomicAdd(&g_acc[1], (double)redn[0]);
    }
}

// ---------------------------------------------------------------
__global__ void finalize_kernel(float* __restrict__ out) {
    double p = g_acc[0];
    double n = g_acc[1];
    const double invN2 = 1.0 / ((double)N_BATCH * (double)N_BATCH);
    out[0] = (float)(p * invN2);   // mean(pos)
    out[1] = (float)(n * invN2);   // mean(neg)
    out[2] = (float)p;             // sum(pos)
    out[3] = (float)n;             // sum(neg)
}

// ---------------------------------------------------------------
extern "C" void kernel_launch(void* const* d_in, const int* in_sizes, int n_in,
                              void* d_out, int out_size) {
    const float* mu     = (const float*)d_in[0];
    const float* var    = (const float*)d_in[1];
    const int*   labels = (const int*)d_in[2];
    float* out = (float*)d_out;

    init_kernel<<<1, 1>>>();
    precompute_kernel<<<N_BATCH, 64>>>(mu, var);
    dim3 grid(NBLK, NBLK);        // upper triangle filtered in-kernel
    pair_kernel<<<grid, 256>>>(labels);
    finalize_kernel<<<1, 1>>>(out);
}

// round 4
// speedup vs baseline: 1.7212x; 1.7212x over previous
#include <cuda_runtime.h>
#include <cstdint>
#include <math.h>

#define N_BATCH 4096
#define D_FEAT  64
#define KDIM    256                       // packed [u, -2mu, a, b]
#define TILE    128
#define NBLK    (N_BATCH / TILE)          // 32
#define NPAIRS  (NBLK * (NBLK + 1) / 2)   // 528
#define KC      32                        // k-chunk staged in smem
#define LDST    36                        // smem row stride (floats), conflict-free

// ---- scratch (static device globals; no allocation allowed) ----
__device__ __align__(256) float g_V[N_BATCH * KDIM];   // tf32-rounded packed vectors
__device__ __align__(256) float g_C[N_BATCH];
__device__ __align__(256) float g_P[N_BATCH];
__device__ __align__(256) float g_RP[N_BATCH];
__device__ double g_acc[2];

// ---- smem float offsets ----
// sI[2]: 0 / 4608, sJ[2]: 9216 / 13824  (128 rows x 36 floats each)
// rowd: 18432 (128 float4), cold: 18944 (128 float4), red: 19456
#define OFF_J    9216
#define OFF_ROWD 18432
#define OFF_COLD 18944
#define OFF_REDP 19456
#define OFF_REDN 19472
#define SM_FLOATS 19488
#define SM_BYTES  (SM_FLOATS * 4)

// ---------------------------------------------------------------
__global__ void init_kernel() { g_acc[0] = 0.0; g_acc[1] = 0.0; }

// 4096 blocks x 128 threads
__global__ void precompute_kernel(const float* __restrict__ mu,
                                  const float* __restrict__ var) {
    int row = blockIdx.x;
    int tid = threadIdx.x;
    int d   = tid & 63;
    float v  = var[row * D_FEAT + d];
    float m  = mu [row * D_FEAT + d];
    float iv = 1.0f / v;
    float x, y;
    if (tid < 64) { x = v + m * m;  y = iv; }      // -> V[d], V[128+d]
    else          { x = -2.0f * m;  y = m * iv; }  // -> V[64+dd], V[192+dd]
    uint32_t xr, yr;
    asm("cvt.rna.tf32.f32 %0, %1;" : "=r"(xr) : "f"(x));
    asm("cvt.rna.tf32.f32 %0, %1;" : "=r"(yr) : "f"(y));
    uint32_t* Vr = (uint32_t*)g_V;
    Vr[row * KDIM + tid]       = xr;
    Vr[row * KDIM + 128 + tid] = yr;

    __shared__ float sc[64];
    __shared__ float sp[64];
    if (tid < 64) { sc[tid] = m * m * iv; sp[tid] = v; }
    __syncthreads();
    #pragma unroll
    for (int s = 32; s > 0; s >>= 1) {
        if (tid < s) { sc[tid] += sc[tid + s]; sp[tid] *= sp[tid + s]; }
        __syncthreads();
    }
    if (tid == 0) {
        g_C[row]  = sc[0];
        g_P[row]  = sp[0];
        g_RP[row] = 1.0f / (sp[0] + 1e-8f);
    }
}

// ---------------------------------------------------------------
__device__ __forceinline__ void ldg_chunk(float4* regI, float4* regJ,
                                          int baseI, int baseJ, int c, int tid) {
    int cJ = (c + 4) & 7;   // J side uses V rotated by 128 (swap A<->B halves)
    #pragma unroll
    for (int it = 0; it < 4; it++) {
        int idx = tid + it * 256;
        int r = idx >> 3, c8 = idx & 7;
        regI[it] = *(const float4*)(g_V + (size_t)(baseI + r) * KDIM + c  * 32 + c8 * 4);
        regJ[it] = *(const float4*)(g_V + (size_t)(baseJ + r) * KDIM + cJ * 32 + c8 * 4);
    }
}

__device__ __forceinline__ void sts_chunk(float* sm, const float4* regI, const float4* regJ,
                                          int buf, int tid) {
    float* dI = sm + buf * 4608;
    float* dJ = sm + OFF_J + buf * 4608;
    #pragma unroll
    for (int it = 0; it < 4; it++) {
        int idx = tid + it * 256;
        int r = idx >> 3, c8 = idx & 7;
        *(float4*)(dI + r * LDST + c8 * 4) = regI[it];
        *(float4*)(dJ + r * LDST + c8 * 4) = regJ[it];
    }
}

__device__ __forceinline__ void mma_chunk(const float* sm, int buf, int wm, int wn,
                                          int lane, float acc[4][4][4]) {
    const uint32_t* pA = (const uint32_t*)(sm + buf * 4608);
    const uint32_t* pB = (const uint32_t*)(sm + OFF_J + buf * 4608);
    int r4 = lane >> 2, c4 = lane & 3;
    #pragma unroll
    for (int kk = 0; kk < 4; kk++) {
        uint32_t a[4][4], b[4][2];
        #pragma unroll
        for (int tm = 0; tm < 4; tm++) {
            int base = (wm * 64 + tm * 16 + r4) * LDST + kk * 8 + c4;
            a[tm][0] = pA[base];
            a[tm][1] = pA[base + 8 * LDST];
            a[tm][2] = pA[base + 4];
            a[tm][3] = pA[base + 8 * LDST + 4];
        }
        #pragma unroll
        for (int tn = 0; tn < 4; tn++) {
            int base = (wn * 32 + tn * 8 + r4) * LDST + kk * 8 + c4;
            b[tn][0] = pB[base];
            b[tn][1] = pB[base + 4];
        }
        #pragma unroll
        for (int tm = 0; tm < 4; tm++)
            #pragma unroll
            for (int tn = 0; tn < 4; tn++)
                asm volatile(
                    "mma.sync.aligned.m16n8k8.row.col.f32.tf32.tf32.f32 "
                    "{%0,%1,%2,%3},{%4,%5,%6,%7},{%8,%9},{%0,%1,%2,%3};"
                    : "+f"(acc[tm][tn][0]), "+f"(acc[tm][tn][1]),
                      "+f"(acc[tm][tn][2]), "+f"(acc[tm][tn][3])
                    : "r"(a[tm][0]), "r"(a[tm][1]), "r"(a[tm][2]), "r"(a[tm][3]),
                      "r"(b[tn][0]), "r"(b[tn][1]));
    }
}

__device__ __forceinline__ void ep_elem(float S, float4 R, float4 C, int r, int cl,
                                        bool diag, float& pos, float& neg) {
    // R = (0.25*c_i, p_i, rp_i, label_i) ; C = (0.25*p_j, 0.25*rp_j, 0.25*c_j-32, label_j)
    float sym = fmaf(0.25f, S, R.x) + fmaf(R.z, C.x, fmaf(R.y, C.y, C.z));
    float sig = __fdividef(1.0f, 1.0f + __expf(-sym));
    float w = (!diag || (r < cl)) ? 2.0f : 0.0f;
    float t = w * sig;
    if (__float_as_int(R.w) == __float_as_int(C.w)) pos += t; else neg += t;
}

extern __shared__ __align__(16) float sm_dyn[];

__global__ void __launch_bounds__(256)
pair_kernel(const int* __restrict__ labels) {
    float* sm = sm_dyn;
    int tid  = threadIdx.x;
    int wid  = tid >> 5;
    int lane = tid & 31;
    int wm = wid & 1;        // warp M position (0..1) -> 64 rows
    int wn = wid >> 1;       // warp N position (0..3) -> 32 cols

    // decode upper-triangular block pair
    int t = blockIdx.x, bi = 0;
    while (t >= NBLK - bi) { t -= NBLK - bi; bi++; }
    int bj = bi + t;
    int baseI = bi * TILE;
    int baseJ = bj * TILE;

    float acc[4][4][4];
    #pragma unroll
    for (int i = 0; i < 4; i++)
        #pragma unroll
        for (int j = 0; j < 4; j++)
            #pragma unroll
            for (int k = 0; k < 4; k++) acc[i][j][k] = 0.0f;

    float4 regI[4], regJ[4];
    ldg_chunk(regI, regJ, baseI, baseJ, 0, tid);
    sts_chunk(sm, regI, regJ, 0, tid);
    __syncthreads();

    #pragma unroll
    for (int c = 0; c < 8; c++) {
        if (c < 7) ldg_chunk(regI, regJ, baseI, baseJ, c + 1, tid);
        mma_chunk(sm, c & 1, wm, wn, lane, acc);
        if (c < 7) sts_chunk(sm, regI, regJ, (c + 1) & 1, tid);
        __syncthreads();
    }

    // ---- epilogue ----
    float4* rowd = (float4*)(sm + OFF_ROWD);
    float4* cold = (float4*)(sm + OFF_COLD);
    if (tid < 128) {
        int gi = baseI + tid, gj = baseJ + tid;
        rowd[tid] = make_float4(0.25f * g_C[gi], g_P[gi], g_RP[gi],
                                __int_as_float(labels[gi]));
        cold[tid] = make_float4(0.25f * g_P[gj], 0.25f * g_RP[gj],
                                0.25f * g_C[gj] - 32.0f, __int_as_float(labels[gj]));
    }
    __syncthreads();

    bool diag = (bi == bj);
    float pos = 0.0f, neg = 0.0f;
    int r0 = wm * 64 + (lane >> 2);
    int c0 = wn * 32 + 2 * (lane & 3);
    #pragma unroll
    for (int tm = 0; tm < 4; tm++) {
        int r1 = r0 + tm * 16, r2 = r1 + 8;
        float4 R1 = rowd[r1], R2 = rowd[r2];
        #pragma unroll
        for (int tn = 0; tn < 4; tn++) {
            int ca = c0 + tn * 8;
            float4 C1 = cold[ca], C2 = cold[ca + 1];
            ep_elem(acc[tm][tn][0], R1, C1, r1, ca,     diag, pos, neg);
            ep_elem(acc[tm][tn][1], R1, C2, r1, ca + 1, diag, pos, neg);
            ep_elem(acc[tm][tn][2], R2, C1, r2, ca,     diag, pos, neg);
            ep_elem(acc[tm][tn][3], R2, C2, r2, ca + 1, diag, pos, neg);
        }
    }

    // warp reduce, then block reduce
    #pragma unroll
    for (int off = 16; off; off >>= 1) {
        pos += __shfl_xor_sync(0xffffffffu, pos, off);
        neg += __shfl_xor_sync(0xffffffffu, neg, off);
    }
    float* redp = sm + OFF_REDP;
    float* redn = sm + OFF_REDN;
    if (lane == 0) { redp[wid] = pos; redn[wid] = neg; }
    __syncthreads();
    if (tid == 0) {
        float p = 0.0f, n = 0.0f;
        #pragma unroll
        for (int i = 0; i < 8; i++) { p += redp[i]; n += redn[i]; }
        atomicAdd(&g_acc[0], (double)p);
        atomicAdd(&g_acc[1], (double)n);
    }
}

// ---------------------------------------------------------------
__global__ void finalize_kernel(float* __restrict__ out) {
    double p = g_acc[0];
    double n = g_acc[1];
    const double invN2 = 1.0 / ((double)N_BATCH * (double)N_BATCH);
    out[0] = (float)(p * invN2);
    out[1] = (float)(n * invN2);
    out[2] = (float)p;
    out[3] = (float)n;
}

// ---------------------------------------------------------------
extern "C" void kernel_launch(void* const* d_in, const int* in_sizes, int n_in,
                              void* d_out, int out_size) {
    const float* mu     = (const float*)d_in[0];
    const float* var    = (const float*)d_in[1];
    const int*   labels = (const int*)d_in[2];
    float* out = (float*)d_out;

    cudaFuncSetAttribute(pair_kernel, cudaFuncAttributeMaxDynamicSharedMemorySize, SM_BYTES);

    init_kernel<<<1, 1>>>();
    precompute_kernel<<<N_BATCH, 128>>>(mu, var);
    pair_kernel<<<NPAIRS, 256, SM_BYTES>>>(labels);
    finalize_kernel<<<1, 1>>>(out);
}

// round 5
// speedup vs baseline: 3.5009x; 2.0340x over previous
#include <cuda_runtime.h>
#include <cstdint>
#include <math.h>

#define N_BATCH 4096
#define D_FEAT  64
#define KDIM    256                       // packed [u, -2mu, a, b]
#define TILE    128
#define NBLK    (N_BATCH / TILE)          // 32
#define NPAIRS  (NBLK * (NBLK + 1) / 2)   // 528
#define NCHUNK  8                         // k chunks of 32
#define STAGES  3

// ---- scratch (static device globals; no allocation allowed) ----
// A-operand layout: [blk 32][chunk 8][rb 8][kb 4][lane 32][slot 4] floats
__device__ __align__(256) float g_VA[N_BATCH * KDIM];
// B-operand layout (k rotated by 128): [blk 32][chunk 8][nb 16][kb 4][lane 32][slot 2]
__device__ __align__(256) float g_VB[N_BATCH * KDIM];
__device__ __align__(256) float g_C[N_BATCH];
__device__ __align__(256) float g_P[N_BATCH];
__device__ __align__(256) float g_RP[N_BATCH];
__device__ double g_acc[2];
__device__ unsigned g_done;

// ---- smem: 3 stages x 32KB (A 16KB + B 16KB); epilogue reuses stage 0 ----
#define STAGE_FLOATS 8192
#define SM_FLOATS   (STAGES * STAGE_FLOATS)
#define SM_BYTES    (SM_FLOATS * 4)
#define OFF_ROWD 0      // 128 float4
#define OFF_COLD 2048   // 128 float4
#define OFF_REDP 4096
#define OFF_REDN 4104

// ---------------------------------------------------------------
__device__ __forceinline__ uint32_t smem_u32(const void* p) {
    uint32_t a;
    asm("{ .reg .u64 t; cvta.to.shared.u64 t, %1; cvt.u32.u64 %0, t; }" : "=r"(a) : "l"(p));
    return a;
}
__device__ __forceinline__ void cp16(uint32_t dst, const void* src) {
    asm volatile("cp.async.cg.shared.global [%0], [%1], 16;" :: "r"(dst), "l"(src));
}
#define CP_COMMIT() asm volatile("cp.async.commit_group;" ::: "memory")
#define CP_WAIT(n)  asm volatile("cp.async.wait_group %0;" :: "n"(n) : "memory")

// ---------------------------------------------------------------
// 4096 blocks x 128 threads: tf32-round, write fragment-permuted operands
__global__ void precompute_kernel(const float* __restrict__ mu,
                                  const float* __restrict__ var) {
    int row = blockIdx.x;
    int tid = threadIdx.x;
    if (row == 0 && tid == 0) { g_acc[0] = 0.0; g_acc[1] = 0.0; }
    int d = tid & 63;
    float v  = var[row * D_FEAT + d];
    float m  = mu [row * D_FEAT + d];
    float iv = 1.0f / v;
    float x, y;
    if (tid < 64) { x = v + m * m;  y = iv; }      // k = tid, k = 128+tid
    else          { x = -2.0f * m;  y = m * iv; }
    uint32_t xr, yr;
    asm("cvt.rna.tf32.f32 %0, %1;" : "=r"(xr) : "f"(x));
    asm("cvt.rna.tf32.f32 %0, %1;" : "=r"(yr) : "f"(y));

    int b = row >> 7, r = row & 127;
    int rb = r >> 4, ri = r & 15;
    int nb = r >> 3, ji = r & 7;
    uint32_t* VA = (uint32_t*)g_VA;
    uint32_t* VB = (uint32_t*)g_VB;
    uint32_t vals[2] = { xr, yr };
    int ks[2] = { tid, 128 + tid };
    #pragma unroll
    for (int q = 0; q < 2; q++) {
        int k = ks[q];
        int c  = k >> 5, kc = k & 31, kb = kc >> 3, kw = kc & 7;
        int cB = (c + 4) & 7;   // J-side rotation baked into B layout
        int laneA = (ri & 7) * 4 + (kw & 3);
        int slotA = (ri >> 3) + 2 * (kw >> 2);
        size_t offA = ((((size_t)b * 8 + c) * 8 + rb) * 4 + kb) * 128 + laneA * 4 + slotA;
        VA[offA] = vals[q];
        int laneB = ji * 4 + (kw & 3);
        int slotB = kw >> 2;
        size_t offB = ((((size_t)b * 8 + cB) * 16 + nb) * 4 + kb) * 64 + laneB * 2 + slotB;
        VB[offB] = vals[q];
    }

    __shared__ float sc[64];
    __shared__ float sp[64];
    if (tid < 64) { sc[tid] = m * m * iv; sp[tid] = v; }
    __syncthreads();
    #pragma unroll
    for (int s = 32; s > 0; s >>= 1) {
        if (tid < s) { sc[tid] += sc[tid + s]; sp[tid] *= sp[tid + s]; }
        __syncthreads();
    }
    if (tid == 0) {
        g_C[row]  = sc[0];
        g_P[row]  = sp[0];
        g_RP[row] = 1.0f / (sp[0] + 1e-8f);
    }
}

// ---------------------------------------------------------------
__device__ __forceinline__ void issue_chunk(uint32_t smbase, int stage,
                                            int bi, int bj, int c, int tid) {
    const float* srcA = g_VA + ((size_t)bi * 8 + c) * 4096;
    const float* srcB = g_VB + ((size_t)bj * 8 + c) * 4096;
    uint32_t dst = smbase + stage * (STAGE_FLOATS * 4);
    #pragma unroll
    for (int it = 0; it < 4; it++) {
        int idx = tid + it * 256;
        cp16(dst + idx * 16,         srcA + idx * 4);
        cp16(dst + 16384 + idx * 16, srcB + idx * 4);
    }
    CP_COMMIT();
}

__device__ __forceinline__ void mma_chunk(const float* sm, int stage, int wm, int wn,
                                          int lane, float acc[4][4][4]) {
    const float* pA = sm + stage * STAGE_FLOATS;
    const float* pB = pA + 4096;
    #pragma unroll
    for (int kk = 0; kk < 4; kk++) {
        uint32_t a[4][4], b[4][2];
        #pragma unroll
        for (int tm = 0; tm < 4; tm++) {
            int rb = wm * 4 + tm;
            const uint4 va = *(const uint4*)(pA + ((rb * 4 + kk) * 32 + lane) * 4);
            a[tm][0] = va.x; a[tm][1] = va.y; a[tm][2] = va.z; a[tm][3] = va.w;
        }
        #pragma unroll
        for (int tn = 0; tn < 4; tn++) {
            int nb = wn * 4 + tn;
            const uint2 vb = *(const uint2*)(pB + ((nb * 4 + kk) * 32 + lane) * 2);
            b[tn][0] = vb.x; b[tn][1] = vb.y;
        }
        #pragma unroll
        for (int tm = 0; tm < 4; tm++)
            #pragma unroll
            for (int tn = 0; tn < 4; tn++)
                asm volatile(
                    "mma.sync.aligned.m16n8k8.row.col.f32.tf32.tf32.f32 "
                    "{%0,%1,%2,%3},{%4,%5,%6,%7},{%8,%9},{%0,%1,%2,%3};"
                    : "+f"(acc[tm][tn][0]), "+f"(acc[tm][tn][1]),
                      "+f"(acc[tm][tn][2]), "+f"(acc[tm][tn][3])
                    : "r"(a[tm][0]), "r"(a[tm][1]), "r"(a[tm][2]), "r"(a[tm][3]),
                      "r"(b[tn][0]), "r"(b[tn][1]));
    }
}

__device__ __forceinline__ void ep_elem(float S, float4 R, float4 C, int r, int cl,
                                        bool diag, float& pos, float& neg) {
    float sym = fmaf(0.25f, S, R.x) + fmaf(R.z, C.x, fmaf(R.y, C.y, C.z));
    float sig = __fdividef(1.0f, 1.0f + __expf(-sym));
    float w = (!diag || (r < cl)) ? 2.0f : 0.0f;
    float t = w * sig;
    if (__float_as_int(R.w) == __float_as_int(C.w)) pos += t; else neg += t;
}

extern __shared__ __align__(16) float sm_dyn[];

__global__ void __launch_bounds__(256, 2)
pair_kernel(const int* __restrict__ labels, float* __restrict__ out) {
    float* sm = sm_dyn;
    uint32_t smb = smem_u32(sm);
    int tid  = threadIdx.x;
    int wid  = tid >> 5;
    int lane = tid & 31;
    int wm = wid & 1;
    int wn = wid >> 1;

    int t = blockIdx.x, bi = 0;
    while (t >= NBLK - bi) { t -= NBLK - bi; bi++; }
    int bj = bi + t;

    float acc[4][4][4];
    #pragma unroll
    for (int i = 0; i < 4; i++)
        #pragma unroll
        for (int j = 0; j < 4; j++)
            #pragma unroll
            for (int k = 0; k < 4; k++) acc[i][j][k] = 0.0f;

    issue_chunk(smb, 0, bi, bj, 0, tid);
    issue_chunk(smb, 1, bi, bj, 1, tid);

    #pragma unroll
    for (int c = 0; c < NCHUNK; c++) {
        if (c == NCHUNK - 1) CP_WAIT(0); else CP_WAIT(1);
        __syncthreads();
        if (c < NCHUNK - 2)
            issue_chunk(smb, (c + 2) % STAGES, bi, bj, c + 2, tid);
        mma_chunk(sm, c % STAGES, wm, wn, lane, acc);
    }

    // ---- epilogue (reuses stage-0 smem) ----
    __syncthreads();
    float4* rowd = (float4*)(sm + OFF_ROWD);
    float4* cold = (float4*)(sm + OFF_COLD);
    if (tid < 128) {
        int gi = bi * TILE + tid, gj = bj * TILE + tid;
        rowd[tid] = make_float4(0.25f * g_C[gi], g_P[gi], g_RP[gi],
                                __int_as_float(labels[gi]));
        cold[tid] = make_float4(0.25f * g_P[gj], 0.25f * g_RP[gj],
                                0.25f * g_C[gj] - 32.0f, __int_as_float(labels[gj]));
    }
    __syncthreads();

    bool diag = (bi == bj);
    float pos = 0.0f, neg = 0.0f;
    int r0 = wm * 64 + (lane >> 2);
    int c0 = wn * 32 + 2 * (lane & 3);
    #pragma unroll
    for (int tm = 0; tm < 4; tm++) {
        int r1 = r0 + tm * 16, r2 = r1 + 8;
        float4 R1 = rowd[r1], R2 = rowd[r2];
        #pragma unroll
        for (int tn = 0; tn < 4; tn++) {
            int ca = c0 + tn * 8;
            float4 C1 = cold[ca], C2 = cold[ca + 1];
            ep_elem(acc[tm][tn][0], R1, C1, r1, ca,     diag, pos, neg);
            ep_elem(acc[tm][tn][1], R1, C2, r1, ca + 1, diag, pos, neg);
            ep_elem(acc[tm][tn][2], R2, C1, r2, ca,     diag, pos, neg);
            ep_elem(acc[tm][tn][3], R2, C2, r2, ca + 1, diag, pos, neg);
        }
    }

    #pragma unroll
    for (int off = 16; off; off >>= 1) {
        pos += __shfl_xor_sync(0xffffffffu, pos, off);
        neg += __shfl_xor_sync(0xffffffffu, neg, off);
    }
    float* redp = sm + OFF_REDP;
    float* redn = sm + OFF_REDN;
    if (lane == 0) { redp[wid] = pos; redn[wid] = neg; }
    __syncthreads();
    if (tid == 0) {
        float p = 0.0f, n = 0.0f;
        #pragma unroll
        for (int i = 0; i < 8; i++) { p += redp[i]; n += redn[i]; }
        atomicAdd(&g_acc[0], (double)p);
        atomicAdd(&g_acc[1], (double)n);
        __threadfence();
        unsigned v = atomicAdd(&g_done, 1u);
        if (v == NPAIRS - 1) {               // last CTA finalizes
            g_done = 0;
            double P = g_acc[0], N = g_acc[1];
            const double invN2 = 1.0 / ((double)N_BATCH * (double)N_BATCH);
            out[0] = (float)(P * invN2);
            out[1] = (float)(N * invN2);
            out[2] = (float)P;
            out[3] = (float)N;
        }
    }
}

// ---------------------------------------------------------------
extern "C" void kernel_launch(void* const* d_in, const int* in_sizes, int n_in,
                              void* d_out, int out_size) {
    const float* mu     = (const float*)d_in[0];
    const float* var    = (const float*)d_in[1];
    const int*   labels = (const int*)d_in[2];
    float* out = (float*)d_out;

    cudaFuncSetAttribute(pair_kernel, cudaFuncAttributeMaxDynamicSharedMemorySize, SM_BYTES);

    precompute_kernel<<<N_BATCH, 128>>>(mu, var);
    pair_kernel<<<NPAIRS, 256, SM_BYTES>>>(labels, out);
}

// round 6
// speedup vs baseline: 3.5278x; 1.0077x over previous
#include <cuda_runtime.h>
#include <cstdint>
#include <math.h>

#define N_BATCH 4096
#define D_FEAT  64
#define KDIM    256                       // packed [u, -2mu, a, b]
#define TILE    128
#define NBLK    (N_BATCH / TILE)          // 32
#define NPAIRS  (NBLK * (NBLK + 1) / 2)   // 528
#define NCHUNK  8                         // k chunks of 32
#define STAGES  3

// ---- scratch (static device globals; no allocation allowed) ----
// A-operand layout: [blk 32][chunk 8][rb 8][kb 4][lane 32][slot 4] floats
__device__ __align__(256) float g_VA[N_BATCH * KDIM];
// B-operand layout (k rotated by 128): [blk 32][chunk 8][nb 16][kb2 2][lane 32][slot 4]
// slot = (kk&1)*2 + quad  -> one LDS.128 carries two kk steps
__device__ __align__(256) float g_VB[N_BATCH * KDIM];
__device__ __align__(256) float g_C[N_BATCH];
__device__ __align__(256) float g_P[N_BATCH];
__device__ __align__(256) float g_RP[N_BATCH];
__device__ double g_acc[2];
__device__ unsigned g_done;

// ---- smem: 3 stages x 32KB (A 16KB + B 16KB); epilogue reuses stage 0 ----
#define STAGE_FLOATS 8192
#define SM_FLOATS   (STAGES * STAGE_FLOATS)
#define SM_BYTES    (SM_FLOATS * 4)
#define OFF_ROWD 0      // 128 float4
#define OFF_COLD 2048   // 128 float4
#define OFF_REDP 4096
#define OFF_REDN 4104

// ---------------------------------------------------------------
__device__ __forceinline__ uint32_t smem_u32(const void* p) {
    uint32_t a;
    asm("{ .reg .u64 t; cvta.to.shared.u64 t, %1; cvt.u32.u64 %0, t; }" : "=r"(a) : "l"(p));
    return a;
}
__device__ __forceinline__ void cp16(uint32_t dst, const void* src) {
    asm volatile("cp.async.cg.shared.global [%0], [%1], 16;" :: "r"(dst), "l"(src));
}
#define CP_COMMIT() asm volatile("cp.async.commit_group;" ::: "memory")
#define CP_WAIT(n)  asm volatile("cp.async.wait_group %0;" :: "n"(n) : "memory")

// ---------------------------------------------------------------
// 4096 blocks x 128 threads: tf32-round, write fragment-permuted operands
__global__ void precompute_kernel(const float* __restrict__ mu,
                                  const float* __restrict__ var) {
    int row = blockIdx.x;
    int tid = threadIdx.x;
    if (row == 0 && tid == 0) { g_acc[0] = 0.0; g_acc[1] = 0.0; }
    int d = tid & 63;
    float v  = var[row * D_FEAT + d];
    float m  = mu [row * D_FEAT + d];
    float iv = 1.0f / v;
    float x, y;
    if (tid < 64) { x = v + m * m;  y = iv; }      // k = tid, k = 128+tid
    else          { x = -2.0f * m;  y = m * iv; }
    uint32_t xr, yr;
    asm("cvt.rna.tf32.f32 %0, %1;" : "=r"(xr) : "f"(x));
    asm("cvt.rna.tf32.f32 %0, %1;" : "=r"(yr) : "f"(y));

    int b = row >> 7, r = row & 127;
    int rb = r >> 4, ri = r & 15;
    int nb = r >> 3, ji = r & 7;
    uint32_t* VA = (uint32_t*)g_VA;
    uint32_t* VB = (uint32_t*)g_VB;
    uint32_t vals[2] = { xr, yr };
    int ks[2] = { tid, 128 + tid };
    #pragma unroll
    for (int q = 0; q < 2; q++) {
        int k = ks[q];
        int c  = k >> 5, kc = k & 31, kb = kc >> 3, kw = kc & 7;
        int cB = (c + 4) & 7;   // J-side rotation baked into B layout
        int laneA = (ri & 7) * 4 + (kw & 3);
        int slotA = (ri >> 3) + 2 * (kw >> 2);
        size_t offA = ((((size_t)b * 8 + c) * 8 + rb) * 4 + kb) * 128 + laneA * 4 + slotA;
        VA[offA] = vals[q];
        int laneB = ji * 4 + (kw & 3);
        int slotB = (kb & 1) * 2 + (kw >> 2);
        size_t offB = ((((size_t)b * 8 + cB) * 16 + nb) * 2 + (kb >> 1)) * 128 + laneB * 4 + slotB;
        VB[offB] = vals[q];
    }

    __shared__ float sc[64];
    __shared__ float sp[64];
    if (tid < 64) { sc[tid] = m * m * iv; sp[tid] = v; }
    __syncthreads();
    #pragma unroll
    for (int s = 32; s > 0; s >>= 1) {
        if (tid < s) { sc[tid] += sc[tid + s]; sp[tid] *= sp[tid + s]; }
        __syncthreads();
    }
    if (tid == 0) {
        g_C[row]  = sc[0];
        g_P[row]  = sp[0];
        g_RP[row] = 1.0f / (sp[0] + 1e-8f);
    }
}

// ---------------------------------------------------------------
__device__ __forceinline__ void issue_chunk(uint32_t smbase, int stage,
                                            int bi, int bj, int c, int tid) {
    const float* srcA = g_VA + ((size_t)bi * 8 + c) * 4096;
    const float* srcB = g_VB + ((size_t)bj * 8 + c) * 4096;
    uint32_t dst = smbase + stage * (STAGE_FLOATS * 4);
    #pragma unroll
    for (int it = 0; it < 4; it++) {
        int idx = tid + it * 256;
        cp16(dst + idx * 16,         srcA + idx * 4);
        cp16(dst + 16384 + idx * 16, srcB + idx * 4);
    }
    CP_COMMIT();
}

// fragment loads
__device__ __forceinline__ void lda(const float* pA, int wm, int kk, int lane,
                                    uint32_t a[4][4]) {
    #pragma unroll
    for (int tm = 0; tm < 4; tm++) {
        const uint4 v = *(const uint4*)(pA + (((wm * 4 + tm) * 4 + kk) * 32 + lane) * 4);
        a[tm][0] = v.x; a[tm][1] = v.y; a[tm][2] = v.z; a[tm][3] = v.w;
    }
}
__device__ __forceinline__ void ldb(const float* pB, int wn, int kb2, int lane,
                                    uint32_t b[4][4]) {
    #pragma unroll
    for (int tn = 0; tn < 4; tn++) {
        const uint4 v = *(const uint4*)(pB + (((wn * 4 + tn) * 2 + kb2) * 32 + lane) * 4);
        b[tn][0] = v.x; b[tn][1] = v.y; b[tn][2] = v.z; b[tn][3] = v.w;
    }
}
__device__ __forceinline__ void mma16(const uint32_t a[4][4], const uint32_t b[4][4],
                                      int half, float acc[4][4][4]) {
    #pragma unroll
    for (int tm = 0; tm < 4; tm++)
        #pragma unroll
        for (int tn = 0; tn < 4; tn++)
            asm volatile(
                "mma.sync.aligned.m16n8k8.row.col.f32.tf32.tf32.f32 "
                "{%0,%1,%2,%3},{%4,%5,%6,%7},{%8,%9},{%0,%1,%2,%3};"
                : "+f"(acc[tm][tn][0]), "+f"(acc[tm][tn][1]),
                  "+f"(acc[tm][tn][2]), "+f"(acc[tm][tn][3])
                : "r"(a[tm][0]), "r"(a[tm][1]), "r"(a[tm][2]), "r"(a[tm][3]),
                  "r"(b[tn][half * 2]), "r"(b[tn][half * 2 + 1]));
}

__device__ __forceinline__ void ep_elem(float S, float4 R, float4 C, int r, int cl,
                                        bool diag, float& pos, float& neg) {
    float sym = fmaf(0.25f, S, R.x) + fmaf(R.z, C.x, fmaf(R.y, C.y, C.z));
    float sig = __fdividef(1.0f, 1.0f + __expf(-sym));
    float w = (!diag || (r < cl)) ? 2.0f : 0.0f;
    float t = w * sig;
    if (__float_as_int(R.w) == __float_as_int(C.w)) pos += t; else neg += t;
}

extern __shared__ __align__(16) float sm_dyn[];

__global__ void __launch_bounds__(256, 2)
pair_kernel(const int* __restrict__ labels, float* __restrict__ out) {
    float* sm = sm_dyn;
    uint32_t smb = smem_u32(sm);
    int tid  = threadIdx.x;
    int wid  = tid >> 5;
    int lane = tid & 31;
    int wm = wid & 1;
    int wn = wid >> 1;

    int t = blockIdx.x, bi = 0;
    while (t >= NBLK - bi) { t -= NBLK - bi; bi++; }
    int bj = bi + t;

    float acc[4][4][4];
    #pragma unroll
    for (int i = 0; i < 4; i++)
        #pragma unroll
        for (int j = 0; j < 4; j++)
            #pragma unroll
            for (int k = 0; k < 4; k++) acc[i][j][k] = 0.0f;

    issue_chunk(smb, 0, bi, bj, 0, tid);
    issue_chunk(smb, 1, bi, bj, 1, tid);

    #pragma unroll
    for (int c = 0; c < NCHUNK; c++) {
        if (c == NCHUNK - 1) CP_WAIT(0); else CP_WAIT(1);
        __syncthreads();
        if (c < NCHUNK - 2)
            issue_chunk(smb, (c + 2) % STAGES, bi, bj, c + 2, tid);

        const float* pA = sm + (c % STAGES) * STAGE_FLOATS;
        const float* pB = pA + 4096;
        // software-pipelined: loads run one MMA batch ahead
        uint32_t A0[4][4], A1[4][4], B0[4][4];
        lda(pA, wm, 0, lane, A0);
        ldb(pB, wn, 0, lane, B0);
        lda(pA, wm, 1, lane, A1);
        mma16(A0, B0, 0, acc);        // kk=0
        lda(pA, wm, 2, lane, A0);
        mma16(A1, B0, 1, acc);        // kk=1
        lda(pA, wm, 3, lane, A1);
        ldb(pB, wn, 1, lane, B0);
        mma16(A0, B0, 0, acc);        // kk=2
        mma16(A1, B0, 1, acc);        // kk=3
    }

    // ---- epilogue (reuses stage-0 smem) ----
    __syncthreads();
    float4* rowd = (float4*)(sm + OFF_ROWD);
    float4* cold = (float4*)(sm + OFF_COLD);
    if (tid < 128) {
        int gi = bi * TILE + tid, gj = bj * TILE + tid;
        rowd[tid] = make_float4(0.25f * g_C[gi], g_P[gi], g_RP[gi],
                                __int_as_float(labels[gi]));
        cold[tid] = make_float4(0.25f * g_P[gj], 0.25f * g_RP[gj],
                                0.25f * g_C[gj] - 32.0f, __int_as_float(labels[gj]));
    }
    __syncthreads();

    bool diag = (bi == bj);
    float pos = 0.0f, neg = 0.0f;
    int r0 = wm * 64 + (lane >> 2);
    int c0 = wn * 32 + 2 * (lane & 3);
    #pragma unroll
    for (int tm = 0; tm < 4; tm++) {
        int r1 = r0 + tm * 16, r2 = r1 + 8;
        float4 R1 = rowd[r1], R2 = rowd[r2];
        #pragma unroll
        for (int tn = 0; tn < 4; tn++) {
            int ca = c0 + tn * 8;
            float4 C1 = cold[ca], C2 = cold[ca + 1];
            ep_elem(acc[tm][tn][0], R1, C1, r1, ca,     diag, pos, neg);
            ep_elem(acc[tm][tn][1], R1, C2, r1, ca + 1, diag, pos, neg);
            ep_elem(acc[tm][tn][2], R2, C1, r2, ca,     diag, pos, neg);
            ep_elem(acc[tm][tn][3], R2, C2, r2, ca + 1, diag, pos, neg);
        }
    }

    #pragma unroll
    for (int off = 16; off; off >>= 1) {
        pos += __shfl_xor_sync(0xffffffffu, pos, off);
        neg += __shfl_xor_sync(0xffffffffu, neg, off);
    }
    float* redp = sm + OFF_REDP;
    float* redn = sm + OFF_REDN;
    if (lane == 0) { redp[wid] = pos; redn[wid] = neg; }
    __syncthreads();
    if (tid == 0) {
        float p = 0.0f, n = 0.0f;
        #pragma unroll
        for (int i = 0; i < 8; i++) { p += redp[i]; n += redn[i]; }
        atomicAdd(&g_acc[0], (double)p);
        atomicAdd(&g_acc[1], (double)n);
        __threadfence();
        unsigned v = atomicAdd(&g_done, 1u);
        if (v == NPAIRS - 1) {               // last CTA finalizes
            g_done = 0;
            double P = g_acc[0], N = g_acc[1];
            const double invN2 = 1.0 / ((double)N_BATCH * (double)N_BATCH);
            out[0] = (float)(P * invN2);
            out[1] = (float)(N * invN2);
            out[2] = (float)P;
            out[3] = (float)N;
        }
    }
}

// ---------------------------------------------------------------
extern "C" void kernel_launch(void* const* d_in, const int* in_sizes, int n_in,
                              void* d_out, int out_size) {
    const float* mu     = (const float*)d_in[0];
    const float* var    = (const float*)d_in[1];
    const int*   labels = (const int*)d_in[2];
    float* out = (float*)d_out;

    cudaFuncSetAttribute(pair_kernel, cudaFuncAttributeMaxDynamicSharedMemorySize, SM_BYTES);

    precompute_kernel<<<N_BATCH, 128>>>(mu, var);
    pair_kernel<<<NPAIRS, 256, SM_BYTES>>>(labels, out);
}